// round 1
// baseline (speedup 1.0000x reference)
#include <cuda_runtime.h>
#include <math.h>

// Problem constants
#define BB 2
#define SS 2048
#define DD 1024
#define HH 16
#define HD 64
#define MM (BB*SS)          // 4096 rows for the projections

#define NEGBIG (-1e30f)

// Scratch (no cudaMalloc allowed)
__device__ float g_Q[BB*HH*SS*HD];     // (B,H,S,HD)
__device__ float g_K[BB*HH*SS*HD];
__device__ float g_V[BB*HH*SS*HD];
__device__ float g_attn[BB*SS*DD];     // (B,S,D)

// ---------------------------------------------------------------------------
// SGEMM: out = A(M,K) @ W(N,K)^T + bias, M=4096, N=K=1024.
// 128x128 block tile, BK=8, 256 threads, 8x8 per thread as four 4x4 quads.
// layout==0: out[m*DD+n]; layout==1: head layout out[((b*H+h)*S+s)*HD+hd]
// ---------------------------------------------------------------------------
__global__ __launch_bounds__(256) void sgemm_bias(
    const float* __restrict__ A,
    const float* __restrict__ W,
    const float* __restrict__ bias,
    float* __restrict__ out,
    int layout)
{
    __shared__ float sA[8][132];
    __shared__ float sB[8][132];

    const int tid = threadIdx.x;
    const int tx = tid & 15, ty = tid >> 4;
    const int m0 = blockIdx.y * 128, n0 = blockIdx.x * 128;
    const int lrow = tid >> 1, lhalf = tid & 1;

    float acc[2][2][4][4];
    #pragma unroll
    for (int a = 0; a < 2; a++)
        #pragma unroll
        for (int c = 0; c < 2; c++)
            #pragma unroll
            for (int i = 0; i < 4; i++)
                #pragma unroll
                for (int j = 0; j < 4; j++)
                    acc[a][c][i][j] = 0.f;

    const float* Aip = A + (size_t)(m0 + lrow) * DD + lhalf * 4;
    const float* Wip = W + (size_t)(n0 + lrow) * DD + lhalf * 4;

    for (int k0 = 0; k0 < DD; k0 += 8) {
        float4 av = *(const float4*)(Aip + k0);
        float4 bv = *(const float4*)(Wip + k0);
        __syncthreads();
        sA[lhalf*4+0][lrow] = av.x;
        sA[lhalf*4+1][lrow] = av.y;
        sA[lhalf*4+2][lrow] = av.z;
        sA[lhalf*4+3][lrow] = av.w;
        sB[lhalf*4+0][lrow] = bv.x;
        sB[lhalf*4+1][lrow] = bv.y;
        sB[lhalf*4+2][lrow] = bv.z;
        sB[lhalf*4+3][lrow] = bv.w;
        __syncthreads();
        #pragma unroll
        for (int kk = 0; kk < 8; kk++) {
            float4 a0 = *(const float4*)&sA[kk][ty*4];
            float4 a1 = *(const float4*)&sA[kk][64 + ty*4];
            float4 b0 = *(const float4*)&sB[kk][tx*4];
            float4 b1 = *(const float4*)&sB[kk][64 + tx*4];
            float ar[2][4] = {{a0.x,a0.y,a0.z,a0.w},{a1.x,a1.y,a1.z,a1.w}};
            float br[2][4] = {{b0.x,b0.y,b0.z,b0.w},{b1.x,b1.y,b1.z,b1.w}};
            #pragma unroll
            for (int ri = 0; ri < 2; ri++)
                #pragma unroll
                for (int ci = 0; ci < 2; ci++)
                    #pragma unroll
                    for (int i = 0; i < 4; i++)
                        #pragma unroll
                        for (int j = 0; j < 4; j++)
                            acc[ri][ci][i][j] += ar[ri][i] * br[ci][j];
        }
    }

    #pragma unroll
    for (int ci = 0; ci < 2; ci++) {
        const int n = n0 + ci*64 + tx*4;
        float4 b4 = *(const float4*)&bias[n];
        #pragma unroll
        for (int ri = 0; ri < 2; ri++) {
            #pragma unroll
            for (int i = 0; i < 4; i++) {
                const int m = m0 + ri*64 + ty*4 + i;
                float4 v;
                v.x = acc[ri][ci][i][0] + b4.x;
                v.y = acc[ri][ci][i][1] + b4.y;
                v.z = acc[ri][ci][i][2] + b4.z;
                v.w = acc[ri][ci][i][3] + b4.w;
                if (layout == 0) {
                    *(float4*)&out[(size_t)m*DD + n] = v;
                } else {
                    const int b = m / SS, s = m % SS;
                    const int h = n / HD, hd = n % HD;
                    *(float4*)&out[(((size_t)(b*HH + h))*SS + s)*HD + hd] = v;
                }
            }
        }
    }
}

// ---------------------------------------------------------------------------
// Flash attention, fp32. One block per (b, h, 64-row q tile). 256 threads
// as 16x16; each thread owns a 4(row)x4(col) micro-tile. Causal: key tiles
// kt <= qt only. K stored d-major (transposed) in smem for conflict-free QK^T.
// ---------------------------------------------------------------------------
#define TP 68                    // padded tile row stride (floats)
#define ASMEM (4*64*TP*4 + 2*64*4)

__device__ __forceinline__ float rmax16(float v) {
    v = fmaxf(v, __shfl_xor_sync(0xffffffffu, v, 1));
    v = fmaxf(v, __shfl_xor_sync(0xffffffffu, v, 2));
    v = fmaxf(v, __shfl_xor_sync(0xffffffffu, v, 4));
    v = fmaxf(v, __shfl_xor_sync(0xffffffffu, v, 8));
    return v;
}
__device__ __forceinline__ float rsum16(float v) {
    v += __shfl_xor_sync(0xffffffffu, v, 1);
    v += __shfl_xor_sync(0xffffffffu, v, 2);
    v += __shfl_xor_sync(0xffffffffu, v, 4);
    v += __shfl_xor_sync(0xffffffffu, v, 8);
    return v;
}

extern __shared__ float smem[];

__global__ __launch_bounds__(256) void attn_kernel(const int* __restrict__ am)
{
    float* sQ  = smem;              // [64][TP]  (r, d)
    float* sKT = sQ  + 64*TP;       // [64][TP]  (d, t)   <-- transposed
    float* sV  = sKT + 64*TP;       // [64][TP]  (t, d)
    float* sP  = sV  + 64*TP;       // [64][TP]  (r, t)
    int*   skm = (int*)(sP + 64*TP);  // [64] key mask
    int*   sqm = skm + 64;            // [64] query mask

    const int tid = threadIdx.x;
    const int tx = tid & 15, ty = tid >> 4;
    const int qt = blockIdx.x, h = blockIdx.y, b = blockIdx.z;
    const int q0 = qt * 64;
    const float scale = 0.125f;     // 1/sqrt(64)

    const size_t headoff = ((size_t)(b*HH + h)) * SS * HD;
    const float* Qb = g_Q + headoff;
    const float* Kb = g_K + headoff;
    const float* Vb = g_V + headoff;

    // Load Q tile + query mask
    #pragma unroll
    for (int j = 0; j < 4; j++) {
        int idx = tid + j*256;
        int r = idx >> 4, seg = idx & 15;
        float4 v = *(const float4*)&Qb[(size_t)(q0 + r)*HD + seg*4];
        *(float4*)&sQ[r*TP + seg*4] = v;
    }
    if (tid < 64) sqm[tid] = am[b*SS + q0 + tid];
    __syncthreads();

    const int r0 = ty*4, c0 = tx*4;
    float accO[4][4];
    float m_i[4] = {NEGBIG, NEGBIG, NEGBIG, NEGBIG};
    float l_i[4] = {0.f, 0.f, 0.f, 0.f};
    #pragma unroll
    for (int i = 0; i < 4; i++)
        #pragma unroll
        for (int j = 0; j < 4; j++) accO[i][j] = 0.f;

    for (int kt = 0; kt <= qt; kt++) {
        const int t0 = kt * 64;
        __syncthreads();   // previous iteration done reading tiles
        // K tile, transposed into (d, t)
        #pragma unroll
        for (int j = 0; j < 4; j++) {
            int idx = tid + j*256;
            int t = idx & 63, seg = idx >> 6;
            float4 v = *(const float4*)&Kb[(size_t)(t0 + t)*HD + seg*4];
            sKT[(seg*4+0)*TP + t] = v.x;
            sKT[(seg*4+1)*TP + t] = v.y;
            sKT[(seg*4+2)*TP + t] = v.z;
            sKT[(seg*4+3)*TP + t] = v.w;
        }
        // V tile (t, d)
        #pragma unroll
        for (int j = 0; j < 4; j++) {
            int idx = tid + j*256;
            int t = idx >> 4, seg = idx & 15;
            float4 v = *(const float4*)&Vb[(size_t)(t0 + t)*HD + seg*4];
            *(float4*)&sV[t*TP + seg*4] = v;
        }
        if (tid < 64) skm[tid] = am[b*SS + t0 + tid];
        __syncthreads();

        // S = (Q K^T) for the 4x4 micro-tile
        float4 s4[4];
        #pragma unroll
        for (int i = 0; i < 4; i++) s4[i] = make_float4(0.f,0.f,0.f,0.f);
        #pragma unroll 16
        for (int d = 0; d < 64; d++) {
            float4 kv = *(const float4*)&sKT[d*TP + c0];
            #pragma unroll
            for (int i = 0; i < 4; i++) {
                float qv = sQ[(r0+i)*TP + d];
                s4[i].x += qv * kv.x;
                s4[i].y += qv * kv.y;
                s4[i].z += qv * kv.z;
                s4[i].w += qv * kv.w;
            }
        }

        // mask + online softmax update
        #pragma unroll
        for (int i = 0; i < 4; i++) {
            const int gq = q0 + r0 + i;
            const bool qok = (sqm[r0+i] != 0);
            float sv[4] = {s4[i].x, s4[i].y, s4[i].z, s4[i].w};
            float rowmax = NEGBIG;
            #pragma unroll
            for (int j = 0; j < 4; j++) {
                const int gk = t0 + c0 + j;
                const bool ok = qok && (gk <= gq) && (skm[c0+j] != 0);
                sv[j] = ok ? sv[j] * scale : NEGBIG;
                rowmax = fmaxf(rowmax, sv[j]);
            }
            rowmax = rmax16(rowmax);
            const float mnew = fmaxf(m_i[i], rowmax);
            const float corr = __expf(m_i[i] - mnew);
            float p0 = __expf(sv[0] - mnew);
            float p1 = __expf(sv[1] - mnew);
            float p2 = __expf(sv[2] - mnew);
            float p3 = __expf(sv[3] - mnew);
            float rs = rsum16(p0 + p1 + p2 + p3);
            l_i[i] = l_i[i] * corr + rs;
            m_i[i] = mnew;
            #pragma unroll
            for (int j = 0; j < 4; j++) accO[i][j] *= corr;
            *(float4*)&sP[(r0+i)*TP + c0] = make_float4(p0, p1, p2, p3);
        }
        __syncthreads();

        // O += P @ V
        #pragma unroll 8
        for (int t = 0; t < 64; t += 4) {
            float4 vv0 = *(const float4*)&sV[(t+0)*TP + c0];
            float4 vv1 = *(const float4*)&sV[(t+1)*TP + c0];
            float4 vv2 = *(const float4*)&sV[(t+2)*TP + c0];
            float4 vv3 = *(const float4*)&sV[(t+3)*TP + c0];
            #pragma unroll
            for (int i = 0; i < 4; i++) {
                float4 pr = *(const float4*)&sP[(r0+i)*TP + t];
                accO[i][0] += pr.x*vv0.x + pr.y*vv1.x + pr.z*vv2.x + pr.w*vv3.x;
                accO[i][1] += pr.x*vv0.y + pr.y*vv1.y + pr.z*vv2.y + pr.w*vv3.y;
                accO[i][2] += pr.x*vv0.z + pr.y*vv1.z + pr.z*vv2.z + pr.w*vv3.z;
                accO[i][3] += pr.x*vv0.w + pr.y*vv1.w + pr.z*vv2.w + pr.w*vv3.w;
            }
        }
    }

    // epilogue: normalize, write (B,S,D) scratch
    #pragma unroll
    for (int i = 0; i < 4; i++) {
        const int gq = q0 + r0 + i;
        const float inv = (l_i[i] > 0.f) ? (1.0f / l_i[i]) : 0.f;
        float4 v;
        v.x = accO[i][0] * inv;
        v.y = accO[i][1] * inv;
        v.z = accO[i][2] * inv;
        v.w = accO[i][3] * inv;
        *(float4*)&g_attn[((size_t)(b*SS + gq))*DD + h*HD + c0] = v;
    }
}

// ---------------------------------------------------------------------------
extern "C" void kernel_launch(void* const* d_in, const int* in_sizes, int n_in,
                              void* d_out, int out_size)
{
    (void)in_sizes; (void)n_in; (void)out_size;
    const float* x  = (const float*)d_in[0];
    const int*   am = (const int*)d_in[1];
    const float* Wq = (const float*)d_in[2];
    const float* bq = (const float*)d_in[3];
    const float* Wk = (const float*)d_in[4];
    const float* bk = (const float*)d_in[5];
    const float* Wv = (const float*)d_in[6];
    const float* bv = (const float*)d_in[7];
    const float* Wp = (const float*)d_in[8];
    const float* bp = (const float*)d_in[9];
    float* out = (float*)d_out;

    float *Qp, *Kp, *Vp, *Ap;
    cudaGetSymbolAddress((void**)&Qp, g_Q);
    cudaGetSymbolAddress((void**)&Kp, g_K);
    cudaGetSymbolAddress((void**)&Vp, g_V);
    cudaGetSymbolAddress((void**)&Ap, g_attn);

    cudaFuncSetAttribute(attn_kernel,
                         cudaFuncAttributeMaxDynamicSharedMemorySize, ASMEM);

    dim3 gg(DD/128, MM/128);   // (8, 32)
    sgemm_bias<<<gg, 256>>>(x, Wq, bq, Qp, 1);
    sgemm_bias<<<gg, 256>>>(x, Wk, bk, Kp, 1);
    sgemm_bias<<<gg, 256>>>(x, Wv, bv, Vp, 1);
    attn_kernel<<<dim3(SS/64, HH, BB), 256, ASMEM>>>(am);
    sgemm_bias<<<gg, 256>>>(Ap, Wp, bp, out, 0);
}

// round 3
// speedup vs baseline: 1.4302x; 1.4302x over previous
#include <cuda_runtime.h>
#include <cuda_bf16.h>
#include <cstdint>
#include <math.h>

// Problem constants
#define BB 2
#define SS 2048
#define DD 1024
#define HH 16
#define HD 64
#define MM (BB*SS)

#define NEGBIG (-1e30f)

// ---------------------------------------------------------------------------
// Scratch (no cudaMalloc allowed)
// ---------------------------------------------------------------------------
__device__ float g_Q[BB*HH*SS*HD];     // (B,H,S,HD)
__device__ float g_K[BB*HH*SS*HD];
__device__ float g_V[BB*HH*SS*HD];
__device__ float g_attn[BB*SS*DD];     // (B,S,D)

__device__ __nv_bfloat16 gx_h[MM*DD];
__device__ __nv_bfloat16 gx_l[MM*DD];
__device__ __nv_bfloat16 gw_h[4*DD*DD];
__device__ __nv_bfloat16 gw_l[4*DD*DD];
__device__ __nv_bfloat16 ga_h[MM*DD];
__device__ __nv_bfloat16 ga_l[MM*DD];

// ---------------------------------------------------------------------------
// PTX helpers (plain sm_103-safe: mma.sync / ldmatrix / cp.async)
// ---------------------------------------------------------------------------
__device__ __forceinline__ uint32_t smem_u32(const void* p) {
    uint32_t a;
    asm("{ .reg .u64 t; cvta.to.shared.u64 t, %1; cvt.u32.u64 %0, t; }" : "=r"(a) : "l"(p));
    return a;
}

__device__ __forceinline__ void mma16816(float* c, const uint32_t* a, const uint32_t* b) {
    asm volatile(
        "mma.sync.aligned.m16n8k16.row.col.f32.bf16.bf16.f32 "
        "{%0,%1,%2,%3}, {%4,%5,%6,%7}, {%8,%9}, {%0,%1,%2,%3};"
        : "+f"(c[0]), "+f"(c[1]), "+f"(c[2]), "+f"(c[3])
        : "r"(a[0]), "r"(a[1]), "r"(a[2]), "r"(a[3]), "r"(b[0]), "r"(b[1]));
}

__device__ __forceinline__ void ldsm4(uint32_t* r, uint32_t addr) {
    asm volatile("ldmatrix.sync.aligned.m8n8.x4.shared.b16 {%0,%1,%2,%3}, [%4];"
        : "=r"(r[0]), "=r"(r[1]), "=r"(r[2]), "=r"(r[3]) : "r"(addr));
}

#define CP_ASYNC16(dst, src) \
    asm volatile("cp.async.cg.shared.global [%0], [%1], 16;" :: "r"(dst), "l"(src))
#define CP_COMMIT() asm volatile("cp.async.commit_group;" ::: "memory")
#define CP_WAIT1() asm volatile("cp.async.wait_group 1;" ::: "memory")
#define CP_WAIT0() asm volatile("cp.async.wait_group 0;" ::: "memory")

// ---------------------------------------------------------------------------
// fp32 -> (bf16 hi, bf16 lo) split
// ---------------------------------------------------------------------------
__global__ __launch_bounds__(256) void split_bf16(
    const float* __restrict__ in, __nv_bfloat16* __restrict__ hi,
    __nv_bfloat16* __restrict__ lo, int n)
{
    int i = (blockIdx.x * 256 + threadIdx.x) * 4;
    if (i >= n) return;
    float4 v = *(const float4*)(in + i);
    __nv_bfloat16 h0 = __float2bfloat16(v.x), h1 = __float2bfloat16(v.y);
    __nv_bfloat16 h2 = __float2bfloat16(v.z), h3 = __float2bfloat16(v.w);
    __nv_bfloat16 l0 = __float2bfloat16(v.x - __bfloat162float(h0));
    __nv_bfloat16 l1 = __float2bfloat16(v.y - __bfloat162float(h1));
    __nv_bfloat16 l2 = __float2bfloat16(v.z - __bfloat162float(h2));
    __nv_bfloat16 l3 = __float2bfloat16(v.w - __bfloat162float(h3));
    __nv_bfloat162 hp0 = __nv_bfloat162(h0, h1), hp1 = __nv_bfloat162(h2, h3);
    __nv_bfloat162 lp0 = __nv_bfloat162(l0, l1), lp1 = __nv_bfloat162(l2, l3);
    uint2 hv, lv;
    hv.x = *(uint32_t*)&hp0; hv.y = *(uint32_t*)&hp1;
    lv.x = *(uint32_t*)&lp0; lv.y = *(uint32_t*)&lp1;
    *(uint2*)(hi + i) = hv;
    *(uint2*)(lo + i) = lv;
}

// ---------------------------------------------------------------------------
// Tensor-core GEMM via mma.sync: out[m][n] = sum_k A[m][k]*W[n][k] + bias[n]
// bf16 hi/lo compensated (AhBh + AlBh + AhBl). 128x128 CTA tile, 8 warps,
// warp tile 32x64, K-step 16, cp.async double buffer.
// layout==0: out[m*DD+n]; layout==1: (B,H,S,HD)
// ---------------------------------------------------------------------------
#define PITCHB 48                        // bytes per smem row (16 bf16 + pad)
#define ARR_BYTES (128 * PITCHB)         // 6144
#define STAGE_BYTES (4 * ARR_BYTES)      // Ah, Al, Bh, Bl = 24576
#define GEMM_SMEM (2 * STAGE_BYTES)      // 49152
#define NKSTEP (DD / 16)                 // 64

extern __shared__ char dsm[];

__global__ __launch_bounds__(256)
void tc_gemm(const __nv_bfloat16* __restrict__ Ah, const __nv_bfloat16* __restrict__ Al,
             const __nv_bfloat16* __restrict__ Bh, const __nv_bfloat16* __restrict__ Bl,
             const float* __restrict__ bias, float* __restrict__ out, int layout)
{
    const int tid = threadIdx.x;
    const int wid = tid >> 5, lane = tid & 31;
    const int wm = wid & 3, wn = wid >> 2;          // warp grid 4 x 2
    const int n0 = blockIdx.x * 128, m0 = blockIdx.y * 128;

    const uint32_t smem_base = smem_u32(dsm);

    const __nv_bfloat16* gsrc0 = Ah + (size_t)m0 * DD;
    const __nv_bfloat16* gsrc1 = Al + (size_t)m0 * DD;
    const __nv_bfloat16* gsrc2 = Bh + (size_t)n0 * DD;
    const __nv_bfloat16* gsrc3 = Bl + (size_t)n0 * DD;

    // per-thread cp.async coords (4 chunks, one per array)
    const int lrow = tid >> 1, lhalf = tid & 1;
    const uint32_t sdst = (uint32_t)(lrow * PITCHB + lhalf * 16);
    const size_t goff = (size_t)lrow * DD + lhalf * 8;

    // ldmatrix per-lane offsets (within an array)
    const uint32_t offA = (uint32_t)((lane & 15) * PITCHB + (lane >> 4) * 16);
    const int m8 = lane >> 3;
    const int radd = lane - ((m8 == 1 || m8 == 2) ? 8 : (m8 == 3 ? 16 : 0));
    const uint32_t offB = (uint32_t)(radd * PITCHB + ((m8 & 1) ? 16 : 0));

    float acc[2][8][4];
    #pragma unroll
    for (int i = 0; i < 2; i++)
        #pragma unroll
        for (int j = 0; j < 8; j++)
            #pragma unroll
            for (int k = 0; k < 4; k++) acc[i][j][k] = 0.f;

    // prologue: stage 0
    {
        uint32_t st = smem_base;
        CP_ASYNC16(st + 0*ARR_BYTES + sdst, (const char*)(gsrc0 + goff));
        CP_ASYNC16(st + 1*ARR_BYTES + sdst, (const char*)(gsrc1 + goff));
        CP_ASYNC16(st + 2*ARR_BYTES + sdst, (const char*)(gsrc2 + goff));
        CP_ASYNC16(st + 3*ARR_BYTES + sdst, (const char*)(gsrc3 + goff));
        CP_COMMIT();
    }

    for (int c = 0; c < NKSTEP; c++) {
        if (c + 1 < NKSTEP) {
            uint32_t st = smem_base + ((c + 1) & 1) * STAGE_BYTES;
            size_t go = goff + (size_t)(c + 1) * 16;
            CP_ASYNC16(st + 0*ARR_BYTES + sdst, (const char*)(gsrc0 + go));
            CP_ASYNC16(st + 1*ARR_BYTES + sdst, (const char*)(gsrc1 + go));
            CP_ASYNC16(st + 2*ARR_BYTES + sdst, (const char*)(gsrc2 + go));
            CP_ASYNC16(st + 3*ARR_BYTES + sdst, (const char*)(gsrc3 + go));
            CP_COMMIT();
            CP_WAIT1();
        } else {
            CP_WAIT0();
        }
        __syncthreads();

        const uint32_t sb = smem_base + (c & 1) * STAGE_BYTES;
        const uint32_t aBase = sb + (uint32_t)(wm * 32 * PITCHB) + offA;
        const uint32_t bBase = sb + 2*ARR_BYTES + (uint32_t)(wn * 64 * PITCHB) + offB;

        uint32_t aH[2][4], aL[2][4], bb[4][4];
        ldsm4(aH[0], aBase);
        ldsm4(aH[1], aBase + 16 * PITCHB);
        ldsm4(aL[0], aBase + ARR_BYTES);
        ldsm4(aL[1], aBase + ARR_BYTES + 16 * PITCHB);
        #pragma unroll
        for (int p = 0; p < 4; p++) ldsm4(bb[p], bBase + p * 16 * PITCHB);

        #pragma unroll
        for (int mt = 0; mt < 2; mt++)
            #pragma unroll
            for (int nt = 0; nt < 8; nt++)
                mma16816(acc[mt][nt], aH[mt], &bb[nt >> 1][(nt & 1) * 2]);
        #pragma unroll
        for (int mt = 0; mt < 2; mt++)
            #pragma unroll
            for (int nt = 0; nt < 8; nt++)
                mma16816(acc[mt][nt], aL[mt], &bb[nt >> 1][(nt & 1) * 2]);

        // reload b with Bl
        #pragma unroll
        for (int p = 0; p < 4; p++) ldsm4(bb[p], bBase + ARR_BYTES + p * 16 * PITCHB);
        #pragma unroll
        for (int mt = 0; mt < 2; mt++)
            #pragma unroll
            for (int nt = 0; nt < 8; nt++)
                mma16816(acc[mt][nt], aH[mt], &bb[nt >> 1][(nt & 1) * 2]);

        __syncthreads();
    }

    // epilogue
    const int g = lane >> 2, tig = lane & 3;
    #pragma unroll
    for (int mt = 0; mt < 2; mt++) {
        #pragma unroll
        for (int nt = 0; nt < 8; nt++) {
            const int col = n0 + wn * 64 + nt * 8 + tig * 2;
            const float2 b2 = *(const float2*)&bias[col];
            const int r1 = m0 + wm * 32 + mt * 16 + g;
            const int r2 = r1 + 8;
            float2 v0, v1;
            v0.x = acc[mt][nt][0] + b2.x; v0.y = acc[mt][nt][1] + b2.y;
            v1.x = acc[mt][nt][2] + b2.x; v1.y = acc[mt][nt][3] + b2.y;
            if (layout == 0) {
                *(float2*)&out[(size_t)r1 * DD + col] = v0;
                *(float2*)&out[(size_t)r2 * DD + col] = v1;
            } else {
                const int h = col >> 6, hd = col & 63;
                const int b1b = r1 >> 11, s1 = r1 & 2047;
                const int b2b = r2 >> 11, s2 = r2 & 2047;
                *(float2*)&g_attn[0] = *(float2*)&g_attn[0]; // no-op guard removed below
                *(float2*)&out[(((size_t)(b1b * HH + h)) * SS + s1) * HD + hd] = v0;
                *(float2*)&out[(((size_t)(b2b * HH + h)) * SS + s2) * HD + hd] = v1;
            }
        }
    }
}

// ---------------------------------------------------------------------------
// Flash attention, fp32 (unchanged from R1 passing version)
// ---------------------------------------------------------------------------
#define TP 68
#define ASMEM (4*64*TP*4 + 2*64*4)

__device__ __forceinline__ float rmax16(float v) {
    v = fmaxf(v, __shfl_xor_sync(0xffffffffu, v, 1));
    v = fmaxf(v, __shfl_xor_sync(0xffffffffu, v, 2));
    v = fmaxf(v, __shfl_xor_sync(0xffffffffu, v, 4));
    v = fmaxf(v, __shfl_xor_sync(0xffffffffu, v, 8));
    return v;
}
__device__ __forceinline__ float rsum16(float v) {
    v += __shfl_xor_sync(0xffffffffu, v, 1);
    v += __shfl_xor_sync(0xffffffffu, v, 2);
    v += __shfl_xor_sync(0xffffffffu, v, 4);
    v += __shfl_xor_sync(0xffffffffu, v, 8);
    return v;
}

__global__ __launch_bounds__(256) void attn_kernel(const int* __restrict__ am)
{
    float* sQ  = (float*)dsm;
    float* sKT = sQ  + 64*TP;
    float* sV  = sKT + 64*TP;
    float* sP  = sV  + 64*TP;
    int*   skm = (int*)(sP + 64*TP);
    int*   sqm = skm + 64;

    const int tid = threadIdx.x;
    const int tx = tid & 15, ty = tid >> 4;
    const int qt = blockIdx.x, h = blockIdx.y, b = blockIdx.z;
    const int q0 = qt * 64;
    const float scale = 0.125f;

    const size_t headoff = ((size_t)(b*HH + h)) * SS * HD;
    const float* Qb = g_Q + headoff;
    const float* Kb = g_K + headoff;
    const float* Vb = g_V + headoff;

    #pragma unroll
    for (int j = 0; j < 4; j++) {
        int idx = tid + j*256;
        int r = idx >> 4, seg = idx & 15;
        float4 v = *(const float4*)&Qb[(size_t)(q0 + r)*HD + seg*4];
        *(float4*)&sQ[r*TP + seg*4] = v;
    }
    if (tid < 64) sqm[tid] = am[b*SS + q0 + tid];
    __syncthreads();

    const int r0 = ty*4, c0 = tx*4;
    float accO[4][4];
    float m_i[4] = {NEGBIG, NEGBIG, NEGBIG, NEGBIG};
    float l_i[4] = {0.f, 0.f, 0.f, 0.f};
    #pragma unroll
    for (int i = 0; i < 4; i++)
        #pragma unroll
        for (int j = 0; j < 4; j++) accO[i][j] = 0.f;

    for (int kt = 0; kt <= qt; kt++) {
        const int t0 = kt * 64;
        __syncthreads();
        #pragma unroll
        for (int j = 0; j < 4; j++) {
            int idx = tid + j*256;
            int t = idx & 63, seg = idx >> 6;
            float4 v = *(const float4*)&Kb[(size_t)(t0 + t)*HD + seg*4];
            sKT[(seg*4+0)*TP + t] = v.x;
            sKT[(seg*4+1)*TP + t] = v.y;
            sKT[(seg*4+2)*TP + t] = v.z;
            sKT[(seg*4+3)*TP + t] = v.w;
        }
        #pragma unroll
        for (int j = 0; j < 4; j++) {
            int idx = tid + j*256;
            int t = idx >> 4, seg = idx & 15;
            float4 v = *(const float4*)&Vb[(size_t)(t0 + t)*HD + seg*4];
            *(float4*)&sV[t*TP + seg*4] = v;
        }
        if (tid < 64) skm[tid] = am[b*SS + t0 + tid];
        __syncthreads();

        float4 s4[4];
        #pragma unroll
        for (int i = 0; i < 4; i++) s4[i] = make_float4(0.f,0.f,0.f,0.f);
        #pragma unroll 16
        for (int d = 0; d < 64; d++) {
            float4 kv = *(const float4*)&sKT[d*TP + c0];
            #pragma unroll
            for (int i = 0; i < 4; i++) {
                float qv = sQ[(r0+i)*TP + d];
                s4[i].x += qv * kv.x;
                s4[i].y += qv * kv.y;
                s4[i].z += qv * kv.z;
                s4[i].w += qv * kv.w;
            }
        }

        #pragma unroll
        for (int i = 0; i < 4; i++) {
            const int gq = q0 + r0 + i;
            const bool qok = (sqm[r0+i] != 0);
            float sv[4] = {s4[i].x, s4[i].y, s4[i].z, s4[i].w};
            float rowmax = NEGBIG;
            #pragma unroll
            for (int j = 0; j < 4; j++) {
                const int gk = t0 + c0 + j;
                const bool ok = qok && (gk <= gq) && (skm[c0+j] != 0);
                sv[j] = ok ? sv[j] * scale : NEGBIG;
                rowmax = fmaxf(rowmax, sv[j]);
            }
            rowmax = rmax16(rowmax);
            const float mnew = fmaxf(m_i[i], rowmax);
            const float corr = __expf(m_i[i] - mnew);
            float p0 = __expf(sv[0] - mnew);
            float p1 = __expf(sv[1] - mnew);
            float p2 = __expf(sv[2] - mnew);
            float p3 = __expf(sv[3] - mnew);
            float rs = rsum16(p0 + p1 + p2 + p3);
            l_i[i] = l_i[i] * corr + rs;
            m_i[i] = mnew;
            #pragma unroll
            for (int j = 0; j < 4; j++) accO[i][j] *= corr;
            *(float4*)&sP[(r0+i)*TP + c0] = make_float4(p0, p1, p2, p3);
        }
        __syncthreads();

        #pragma unroll 8
        for (int t = 0; t < 64; t += 4) {
            float4 vv0 = *(const float4*)&sV[(t+0)*TP + c0];
            float4 vv1 = *(const float4*)&sV[(t+1)*TP + c0];
            float4 vv2 = *(const float4*)&sV[(t+2)*TP + c0];
            float4 vv3 = *(const float4*)&sV[(t+3)*TP + c0];
            #pragma unroll
            for (int i = 0; i < 4; i++) {
                float4 pr = *(const float4*)&sP[(r0+i)*TP + t];
                accO[i][0] += pr.x*vv0.x + pr.y*vv1.x + pr.z*vv2.x + pr.w*vv3.x;
                accO[i][1] += pr.x*vv0.y + pr.y*vv1.y + pr.z*vv2.y + pr.w*vv3.y;
                accO[i][2] += pr.x*vv0.z + pr.y*vv1.z + pr.z*vv2.z + pr.w*vv3.z;
                accO[i][3] += pr.x*vv0.w + pr.y*vv1.w + pr.z*vv2.w + pr.w*vv3.w;
            }
        }
    }

    #pragma unroll
    for (int i = 0; i < 4; i++) {
        const int gq = q0 + r0 + i;
        const float inv = (l_i[i] > 0.f) ? (1.0f / l_i[i]) : 0.f;
        float4 v;
        v.x = accO[i][0] * inv;
        v.y = accO[i][1] * inv;
        v.z = accO[i][2] * inv;
        v.w = accO[i][3] * inv;
        *(float4*)&g_attn[((size_t)(b*SS + gq))*DD + h*HD + c0] = v;
    }
}

// ---------------------------------------------------------------------------
extern "C" void kernel_launch(void* const* d_in, const int* in_sizes, int n_in,
                              void* d_out, int out_size)
{
    (void)in_sizes; (void)n_in; (void)out_size;
    const float* x  = (const float*)d_in[0];
    const int*   am = (const int*)d_in[1];
    const float* Wq = (const float*)d_in[2];
    const float* bq = (const float*)d_in[3];
    const float* Wk = (const float*)d_in[4];
    const float* bk = (const float*)d_in[5];
    const float* Wv = (const float*)d_in[6];
    const float* bv = (const float*)d_in[7];
    const float* Wp = (const float*)d_in[8];
    const float* bp = (const float*)d_in[9];
    float* out = (float*)d_out;

    float *Qp, *Kp, *Vp, *Ap;
    __nv_bfloat16 *xh, *xl, *wh, *wl, *ah, *al;
    cudaGetSymbolAddress((void**)&Qp, g_Q);
    cudaGetSymbolAddress((void**)&Kp, g_K);
    cudaGetSymbolAddress((void**)&Vp, g_V);
    cudaGetSymbolAddress((void**)&Ap, g_attn);
    cudaGetSymbolAddress((void**)&xh, gx_h);
    cudaGetSymbolAddress((void**)&xl, gx_l);
    cudaGetSymbolAddress((void**)&wh, gw_h);
    cudaGetSymbolAddress((void**)&wl, gw_l);
    cudaGetSymbolAddress((void**)&ah, ga_h);
    cudaGetSymbolAddress((void**)&al, ga_l);

    cudaFuncSetAttribute(attn_kernel,
                         cudaFuncAttributeMaxDynamicSharedMemorySize, ASMEM);
    cudaFuncSetAttribute(tc_gemm,
                         cudaFuncAttributeMaxDynamicSharedMemorySize, GEMM_SMEM);

    const int NX = MM * DD;    // 4M elems
    const int NW = DD * DD;    // 1M elems

    split_bf16<<<NX/1024, 256>>>(x, xh, xl, NX);
    split_bf16<<<NW/1024, 256>>>(Wq, wh + 0*NW, wl + 0*NW, NW);
    split_bf16<<<NW/1024, 256>>>(Wk, wh + 1*NW, wl + 1*NW, NW);
    split_bf16<<<NW/1024, 256>>>(Wv, wh + 2*NW, wl + 2*NW, NW);
    split_bf16<<<NW/1024, 256>>>(Wp, wh + 3*NW, wl + 3*NW, NW);

    dim3 gg(DD/128, MM/128);   // (8, 32)
    tc_gemm<<<gg, 256, GEMM_SMEM>>>(xh, xl, wh + 0*NW, wl + 0*NW, bq, Qp, 1);
    tc_gemm<<<gg, 256, GEMM_SMEM>>>(xh, xl, wh + 1*NW, wl + 1*NW, bk, Kp, 1);
    tc_gemm<<<gg, 256, GEMM_SMEM>>>(xh, xl, wh + 2*NW, wl + 2*NW, bv, Vp, 1);

    attn_kernel<<<dim3(SS/64, HH, BB), 256, ASMEM>>>(am);

    split_bf16<<<NX/1024, 256>>>(Ap, ah, al, NX);
    tc_gemm<<<gg, 256, GEMM_SMEM>>>(ah, al, wh + 3*NW, wl + 3*NW, bp, out, 0);
}

// round 4
// speedup vs baseline: 2.3174x; 1.6203x over previous
#include <cuda_runtime.h>
#include <cuda_bf16.h>
#include <cstdint>
#include <math.h>

// Problem constants
#define BB 2
#define SS 2048
#define DD 1024
#define HH 16
#define HD 64
#define MM (BB*SS)

#define NEGBIG (-1e30f)

// ---------------------------------------------------------------------------
// Scratch (no cudaMalloc allowed)
// ---------------------------------------------------------------------------
__device__ __nv_bfloat16 gx_h[MM*DD];
__device__ __nv_bfloat16 gx_l[MM*DD];
__device__ __nv_bfloat16 gw_h[4*DD*DD];
__device__ __nv_bfloat16 gw_l[4*DD*DD];
__device__ __nv_bfloat16 gQh[MM*DD];   // (B,H,S,HD) bf16 hi/lo
__device__ __nv_bfloat16 gQl[MM*DD];
__device__ __nv_bfloat16 gKh[MM*DD];
__device__ __nv_bfloat16 gKl[MM*DD];
__device__ __nv_bfloat16 gVh[MM*DD];
__device__ __nv_bfloat16 gVl[MM*DD];
__device__ __nv_bfloat16 ga_h[MM*DD];  // attention out (B,S,D) hi/lo
__device__ __nv_bfloat16 ga_l[MM*DD];

// ---------------------------------------------------------------------------
// PTX helpers (plain sm_103-safe: mma.sync / ldmatrix / cp.async)
// ---------------------------------------------------------------------------
__device__ __forceinline__ uint32_t smem_u32(const void* p) {
    uint32_t a;
    asm("{ .reg .u64 t; cvta.to.shared.u64 t, %1; cvt.u32.u64 %0, t; }" : "=r"(a) : "l"(p));
    return a;
}

__device__ __forceinline__ void mma16816(float* c, const uint32_t* a, const uint32_t* b) {
    asm volatile(
        "mma.sync.aligned.m16n8k16.row.col.f32.bf16.bf16.f32 "
        "{%0,%1,%2,%3}, {%4,%5,%6,%7}, {%8,%9}, {%0,%1,%2,%3};"
        : "+f"(c[0]), "+f"(c[1]), "+f"(c[2]), "+f"(c[3])
        : "r"(a[0]), "r"(a[1]), "r"(a[2]), "r"(a[3]), "r"(b[0]), "r"(b[1]));
}

__device__ __forceinline__ void ldsm4(uint32_t* r, uint32_t addr) {
    asm volatile("ldmatrix.sync.aligned.m8n8.x4.shared.b16 {%0,%1,%2,%3}, [%4];"
        : "=r"(r[0]), "=r"(r[1]), "=r"(r[2]), "=r"(r[3]) : "r"(addr));
}
__device__ __forceinline__ void ldsm4t(uint32_t* r, uint32_t addr) {
    asm volatile("ldmatrix.sync.aligned.m8n8.x4.trans.shared.b16 {%0,%1,%2,%3}, [%4];"
        : "=r"(r[0]), "=r"(r[1]), "=r"(r[2]), "=r"(r[3]) : "r"(addr));
}
__device__ __forceinline__ uint32_t pack_bf16(float lo, float hi) {
    uint32_t d;
    asm("cvt.rn.bf16x2.f32 %0, %1, %2;" : "=r"(d) : "f"(hi), "f"(lo));
    return d;
}
__device__ __forceinline__ float bfround(float v) {
    return __bfloat162float(__float2bfloat16(v));
}

#define CP_ASYNC16(dst, src) \
    asm volatile("cp.async.cg.shared.global [%0], [%1], 16;" :: "r"(dst), "l"(src))
#define CP_COMMIT() asm volatile("cp.async.commit_group;" ::: "memory")
#define CP_WAIT2() asm volatile("cp.async.wait_group 2;" ::: "memory")
#define CP_WAIT1() asm volatile("cp.async.wait_group 1;" ::: "memory")
#define CP_WAIT0() asm volatile("cp.async.wait_group 0;" ::: "memory")

extern __shared__ char dsm[];

// ---------------------------------------------------------------------------
// fp32 -> (bf16 hi, bf16 lo) split
// ---------------------------------------------------------------------------
__global__ __launch_bounds__(256) void split_bf16(
    const float* __restrict__ in, __nv_bfloat16* __restrict__ hi,
    __nv_bfloat16* __restrict__ lo, int n)
{
    int i = (blockIdx.x * 256 + threadIdx.x) * 4;
    if (i >= n) return;
    float4 v = *(const float4*)(in + i);
    __nv_bfloat16 h0 = __float2bfloat16(v.x), h1 = __float2bfloat16(v.y);
    __nv_bfloat16 h2 = __float2bfloat16(v.z), h3 = __float2bfloat16(v.w);
    __nv_bfloat16 l0 = __float2bfloat16(v.x - __bfloat162float(h0));
    __nv_bfloat16 l1 = __float2bfloat16(v.y - __bfloat162float(h1));
    __nv_bfloat16 l2 = __float2bfloat16(v.z - __bfloat162float(h2));
    __nv_bfloat16 l3 = __float2bfloat16(v.w - __bfloat162float(h3));
    __nv_bfloat162 hp0 = __nv_bfloat162(h0, h1), hp1 = __nv_bfloat162(h2, h3);
    __nv_bfloat162 lp0 = __nv_bfloat162(l0, l1), lp1 = __nv_bfloat162(l2, l3);
    uint2 hv, lv;
    hv.x = *(uint32_t*)&hp0; hv.y = *(uint32_t*)&hp1;
    lv.x = *(uint32_t*)&lp0; lv.y = *(uint32_t*)&lp1;
    *(uint2*)(hi + i) = hv;
    *(uint2*)(lo + i) = lv;
}

// ---------------------------------------------------------------------------
// Tensor-core GEMM via mma.sync: out[m][n] = (sum_k A[m][k]*W[n][k] + bias[n])*scale
// bf16 hi/lo compensated. 128x128 CTA tile, 8 warps, warp tile 32x64.
// layout==0: fp32 out[m*DD+n]; layout==2: bf16 hi/lo, head layout (B,H,S,HD)
// ---------------------------------------------------------------------------
#define PITCHB 48
#define ARR_BYTES (128 * PITCHB)
#define STAGE_BYTES (4 * ARR_BYTES)
#define GEMM_SMEM (2 * STAGE_BYTES)
#define NKSTEP (DD / 16)

__global__ __launch_bounds__(256)
void tc_gemm(const __nv_bfloat16* __restrict__ Ah, const __nv_bfloat16* __restrict__ Al,
             const __nv_bfloat16* __restrict__ Bh, const __nv_bfloat16* __restrict__ Bl,
             const float* __restrict__ bias, float* __restrict__ outf,
             __nv_bfloat16* __restrict__ outh, __nv_bfloat16* __restrict__ outl,
             int layout, float scale)
{
    const int tid = threadIdx.x;
    const int wid = tid >> 5, lane = tid & 31;
    const int wm = wid & 3, wn = wid >> 2;
    const int n0 = blockIdx.x * 128, m0 = blockIdx.y * 128;

    const uint32_t smem_base = smem_u32(dsm);

    const __nv_bfloat16* gsrc0 = Ah + (size_t)m0 * DD;
    const __nv_bfloat16* gsrc1 = Al + (size_t)m0 * DD;
    const __nv_bfloat16* gsrc2 = Bh + (size_t)n0 * DD;
    const __nv_bfloat16* gsrc3 = Bl + (size_t)n0 * DD;

    const int lrow = tid >> 1, lhalf = tid & 1;
    const uint32_t sdst = (uint32_t)(lrow * PITCHB + lhalf * 16);
    const size_t goff = (size_t)lrow * DD + lhalf * 8;

    const uint32_t offA = (uint32_t)((lane & 15) * PITCHB + (lane >> 4) * 16);
    const int m8 = lane >> 3;
    const int radd = lane - ((m8 == 1 || m8 == 2) ? 8 : (m8 == 3 ? 16 : 0));
    const uint32_t offB = (uint32_t)(radd * PITCHB + ((m8 & 1) ? 16 : 0));

    float acc[2][8][4];
    #pragma unroll
    for (int i = 0; i < 2; i++)
        #pragma unroll
        for (int j = 0; j < 8; j++)
            #pragma unroll
            for (int k = 0; k < 4; k++) acc[i][j][k] = 0.f;

    {
        uint32_t st = smem_base;
        CP_ASYNC16(st + 0*ARR_BYTES + sdst, (const char*)(gsrc0 + goff));
        CP_ASYNC16(st + 1*ARR_BYTES + sdst, (const char*)(gsrc1 + goff));
        CP_ASYNC16(st + 2*ARR_BYTES + sdst, (const char*)(gsrc2 + goff));
        CP_ASYNC16(st + 3*ARR_BYTES + sdst, (const char*)(gsrc3 + goff));
        CP_COMMIT();
    }

    for (int c = 0; c < NKSTEP; c++) {
        if (c + 1 < NKSTEP) {
            uint32_t st = smem_base + ((c + 1) & 1) * STAGE_BYTES;
            size_t go = goff + (size_t)(c + 1) * 16;
            CP_ASYNC16(st + 0*ARR_BYTES + sdst, (const char*)(gsrc0 + go));
            CP_ASYNC16(st + 1*ARR_BYTES + sdst, (const char*)(gsrc1 + go));
            CP_ASYNC16(st + 2*ARR_BYTES + sdst, (const char*)(gsrc2 + go));
            CP_ASYNC16(st + 3*ARR_BYTES + sdst, (const char*)(gsrc3 + go));
            CP_COMMIT();
            CP_WAIT1();
        } else {
            CP_WAIT0();
        }
        __syncthreads();

        const uint32_t sb = smem_base + (c & 1) * STAGE_BYTES;
        const uint32_t aBase = sb + (uint32_t)(wm * 32 * PITCHB) + offA;
        const uint32_t bBase = sb + 2*ARR_BYTES + (uint32_t)(wn * 64 * PITCHB) + offB;

        uint32_t aH[2][4], aL[2][4], bb[4][4];
        ldsm4(aH[0], aBase);
        ldsm4(aH[1], aBase + 16 * PITCHB);
        ldsm4(aL[0], aBase + ARR_BYTES);
        ldsm4(aL[1], aBase + ARR_BYTES + 16 * PITCHB);
        #pragma unroll
        for (int p = 0; p < 4; p++) ldsm4(bb[p], bBase + p * 16 * PITCHB);

        #pragma unroll
        for (int mt = 0; mt < 2; mt++)
            #pragma unroll
            for (int nt = 0; nt < 8; nt++)
                mma16816(acc[mt][nt], aH[mt], &bb[nt >> 1][(nt & 1) * 2]);
        #pragma unroll
        for (int mt = 0; mt < 2; mt++)
            #pragma unroll
            for (int nt = 0; nt < 8; nt++)
                mma16816(acc[mt][nt], aL[mt], &bb[nt >> 1][(nt & 1) * 2]);

        #pragma unroll
        for (int p = 0; p < 4; p++) ldsm4(bb[p], bBase + ARR_BYTES + p * 16 * PITCHB);
        #pragma unroll
        for (int mt = 0; mt < 2; mt++)
            #pragma unroll
            for (int nt = 0; nt < 8; nt++)
                mma16816(acc[mt][nt], aH[mt], &bb[nt >> 1][(nt & 1) * 2]);

        __syncthreads();
    }

    const int g = lane >> 2, tig = lane & 3;
    #pragma unroll
    for (int mt = 0; mt < 2; mt++) {
        #pragma unroll
        for (int nt = 0; nt < 8; nt++) {
            const int col = n0 + wn * 64 + nt * 8 + tig * 2;
            const float2 b2 = *(const float2*)&bias[col];
            const int r1 = m0 + wm * 32 + mt * 16 + g;
            const int r2 = r1 + 8;
            float v0 = (acc[mt][nt][0] + b2.x) * scale;
            float v1 = (acc[mt][nt][1] + b2.y) * scale;
            float v2 = (acc[mt][nt][2] + b2.x) * scale;
            float v3 = (acc[mt][nt][3] + b2.y) * scale;
            if (layout == 0) {
                float2 w0 = {v0, v1}, w1 = {v2, v3};
                *(float2*)&outf[(size_t)r1 * DD + col] = w0;
                *(float2*)&outf[(size_t)r2 * DD + col] = w1;
            } else {
                const int h = col >> 6, hd = col & 63;
                const int b1b = r1 >> 11, s1 = r1 & 2047;
                const int b2b = r2 >> 11, s2 = r2 & 2047;
                size_t i1 = (((size_t)(b1b * HH + h)) * SS + s1) * HD + hd;
                size_t i2 = (((size_t)(b2b * HH + h)) * SS + s2) * HD + hd;
                __nv_bfloat16 h0 = __float2bfloat16(v0), h1 = __float2bfloat16(v1);
                __nv_bfloat16 h2 = __float2bfloat16(v2), h3 = __float2bfloat16(v3);
                __nv_bfloat162 hp1 = __nv_bfloat162(h0, h1), hp2 = __nv_bfloat162(h2, h3);
                __nv_bfloat162 lp1 = __nv_bfloat162(
                    __float2bfloat16(v0 - __bfloat162float(h0)),
                    __float2bfloat16(v1 - __bfloat162float(h1)));
                __nv_bfloat162 lp2 = __nv_bfloat162(
                    __float2bfloat16(v2 - __bfloat162float(h2)),
                    __float2bfloat16(v3 - __bfloat162float(h3)));
                *(__nv_bfloat162*)&outh[i1] = hp1;
                *(__nv_bfloat162*)&outh[i2] = hp2;
                *(__nv_bfloat162*)&outl[i1] = lp1;
                *(__nv_bfloat162*)&outl[i2] = lp2;
            }
        }
    }
}

// ---------------------------------------------------------------------------
// Flash attention on mma.sync. CTA: 128 q-rows, loop over 64-key tiles.
// 8 warps x 16 q-rows. 3-term hi/lo compensation for QK^T and P.V.
// Scale (1/8) is pre-folded into Q.
// ---------------------------------------------------------------------------
// smem layout (bytes):
//  Qh chunks  : 0      .. 24575   (4 chunk arrays 128x16, pitch 48)
//  Ql chunks  : 24576  .. 49151
//  stage s (s=0,1) at 49152 + s*43008:
//    Kh: +0 (12288 = 4 x 64x16x48/16...), Kl: +12288, Vh: +24576 (64x144), Vl: +33792
//  sqm: 135168 (int[128]); skm: 135680 (int[2][64])
#define ATT_SMEM 136192

__global__ __launch_bounds__(256) void attn_mma(
    const __nv_bfloat16* __restrict__ Qh, const __nv_bfloat16* __restrict__ Ql,
    const __nv_bfloat16* __restrict__ Kh, const __nv_bfloat16* __restrict__ Kl,
    const __nv_bfloat16* __restrict__ Vh, const __nv_bfloat16* __restrict__ Vl,
    const int* __restrict__ am,
    __nv_bfloat16* __restrict__ Oh, __nv_bfloat16* __restrict__ Ol)
{
    const int tid = threadIdx.x, w = tid >> 5, lane = tid & 31;
    const int qt = (int)gridDim.x - 1 - (int)blockIdx.x;   // big tiles first
    const int h = blockIdx.y, b = blockIdx.z;
    const int q0 = qt * 128;
    const int ktmax = 2 * qt + 2;
    const size_t hoff = ((size_t)(b * HH + h)) * SS * HD;
    const __nv_bfloat16 *qhp = Qh + hoff, *qlp = Ql + hoff;
    const __nv_bfloat16 *khp = Kh + hoff, *klp = Kl + hoff;
    const __nv_bfloat16 *vhp = Vh + hoff, *vlp = Vl + hoff;

    const uint32_t sbase = smem_u32(dsm);
    int* sqm = (int*)(dsm + 135168);
    int* skm = (int*)(dsm + 135680);

    // ---- prologue loads ----
    #pragma unroll
    for (int i = 0; i < 4; i++) {
        int e = tid + i * 256; int r = e >> 3, c = e & 7;
        uint32_t d = sbase + (uint32_t)((c >> 1) * 6144 + r * 48 + (c & 1) * 16);
        const size_t g = (size_t)(q0 + r) * HD + c * 8;
        CP_ASYNC16(d, (const char*)(qhp + g));
        CP_ASYNC16(d + 24576, (const char*)(qlp + g));
    }
    CP_COMMIT();

    auto load_kv = [&](int kt) {
        const int t0 = kt * 64;
        uint32_t st = sbase + 49152 + (uint32_t)((kt & 1) * 43008);
        #pragma unroll
        for (int i = 0; i < 2; i++) {
            int e = tid + i * 256; int r = e >> 3, c = e & 7;
            size_t g = (size_t)(t0 + r) * HD + c * 8;
            uint32_t kd = st + (uint32_t)((c >> 1) * 3072 + r * 48 + (c & 1) * 16);
            CP_ASYNC16(kd, (const char*)(khp + g));
            CP_ASYNC16(kd + 12288, (const char*)(klp + g));
            uint32_t vd = st + 24576 + (uint32_t)(r * 144 + c * 16);
            CP_ASYNC16(vd, (const char*)(vhp + g));
            CP_ASYNC16(vd + 9216, (const char*)(vlp + g));
        }
        if (tid < 64) skm[(kt & 1) * 64 + tid] = am[b * SS + t0 + tid];
        CP_COMMIT();
    };
    load_kv(0);
    load_kv(1);
    if (tid < 128) sqm[tid] = am[b * SS + q0 + tid];
    CP_WAIT2();              // Q group done
    __syncthreads();

    // ---- Q fragments (persistent) ----
    const uint32_t offA = (uint32_t)((lane & 15) * 48 + (lane >> 4) * 16);
    const int m8 = lane >> 3;
    const int radd = lane - ((m8 == 1 || m8 == 2) ? 8 : (m8 == 3 ? 16 : 0));
    const uint32_t offB = (uint32_t)(radd * 48 + ((m8 & 1) ? 16 : 0));
    const uint32_t offV = (uint32_t)((((lane & 7) + ((lane >> 3) & 1) * 8)) * 144
                                     + ((lane >> 4) & 1) * 16);

    uint32_t aQh[4][4], aQl[4][4];
    #pragma unroll
    for (int ks = 0; ks < 4; ks++) {
        uint32_t a = sbase + (uint32_t)(ks * 6144 + w * 16 * 48) + offA;
        ldsm4(aQh[ks], a);
        ldsm4(aQl[ks], a + 24576);
    }

    const int g = lane >> 2, tig2 = (lane & 3) * 2;
    const int row0 = w * 16 + g;
    const int grow0 = q0 + row0, grow1 = grow0 + 8;
    const bool qok0 = (sqm[row0] != 0), qok1 = (sqm[row0 + 8] != 0);

    float oacc[8][4];
    #pragma unroll
    for (int i = 0; i < 8; i++)
        #pragma unroll
        for (int j = 0; j < 4; j++) oacc[i][j] = 0.f;
    float m0 = NEGBIG, m1 = NEGBIG, l0 = 0.f, l1 = 0.f;

    for (int kt = 0; kt < ktmax; kt++) {
        if (kt + 1 < ktmax) { CP_WAIT1(); } else { CP_WAIT0(); }
        __syncthreads();
        const uint32_t sb = sbase + 49152 + (uint32_t)((kt & 1) * 43008);
        const int t0 = kt * 64;
        const int* km = skm + (kt & 1) * 64;

        // ---- S = Q K^T (3-term) ----
        float s[8][4];
        #pragma unroll
        for (int i = 0; i < 8; i++)
            #pragma unroll
            for (int j = 0; j < 4; j++) s[i][j] = 0.f;

        #pragma unroll
        for (int ks = 0; ks < 4; ks++) {
            uint32_t kbh[4][4], kbl[4][4];
            #pragma unroll
            for (int p = 0; p < 4; p++) {
                ldsm4(kbh[p], sb + (uint32_t)(ks * 3072 + p * 768) + offB);
                ldsm4(kbl[p], sb + 12288 + (uint32_t)(ks * 3072 + p * 768) + offB);
            }
            #pragma unroll
            for (int nt = 0; nt < 8; nt++) {
                mma16816(s[nt], aQh[ks], &kbh[nt >> 1][(nt & 1) * 2]);
                mma16816(s[nt], aQl[ks], &kbh[nt >> 1][(nt & 1) * 2]);
                mma16816(s[nt], aQh[ks], &kbl[nt >> 1][(nt & 1) * 2]);
            }
        }

        // ---- mask ----
        #pragma unroll
        for (int nt = 0; nt < 8; nt++) {
            int c0 = nt * 8 + tig2;
            int gc0 = t0 + c0, gc1 = gc0 + 1;
            bool k0 = (km[c0] != 0), k1 = (km[c0 + 1] != 0);
            s[nt][0] = (qok0 && k0 && gc0 <= grow0) ? s[nt][0] : NEGBIG;
            s[nt][1] = (qok0 && k1 && gc1 <= grow0) ? s[nt][1] : NEGBIG;
            s[nt][2] = (qok1 && k0 && gc0 <= grow1) ? s[nt][2] : NEGBIG;
            s[nt][3] = (qok1 && k1 && gc1 <= grow1) ? s[nt][3] : NEGBIG;
        }

        // ---- online softmax ----
        float mx0 = NEGBIG, mx1 = NEGBIG;
        #pragma unroll
        for (int nt = 0; nt < 8; nt++) {
            mx0 = fmaxf(mx0, fmaxf(s[nt][0], s[nt][1]));
            mx1 = fmaxf(mx1, fmaxf(s[nt][2], s[nt][3]));
        }
        mx0 = fmaxf(mx0, __shfl_xor_sync(0xffffffffu, mx0, 1));
        mx0 = fmaxf(mx0, __shfl_xor_sync(0xffffffffu, mx0, 2));
        mx1 = fmaxf(mx1, __shfl_xor_sync(0xffffffffu, mx1, 1));
        mx1 = fmaxf(mx1, __shfl_xor_sync(0xffffffffu, mx1, 2));
        const float mn0 = fmaxf(m0, mx0), mn1 = fmaxf(m1, mx1);
        const float corr0 = __expf(m0 - mn0), corr1 = __expf(m1 - mn1);
        m0 = mn0; m1 = mn1;
        float sum0 = 0.f, sum1 = 0.f;
        #pragma unroll
        for (int nt = 0; nt < 8; nt++) {
            s[nt][0] = __expf(s[nt][0] - mn0);
            s[nt][1] = __expf(s[nt][1] - mn0);
            s[nt][2] = __expf(s[nt][2] - mn1);
            s[nt][3] = __expf(s[nt][3] - mn1);
            sum0 += s[nt][0] + s[nt][1];
            sum1 += s[nt][2] + s[nt][3];
        }
        sum0 += __shfl_xor_sync(0xffffffffu, sum0, 1);
        sum0 += __shfl_xor_sync(0xffffffffu, sum0, 2);
        sum1 += __shfl_xor_sync(0xffffffffu, sum1, 1);
        sum1 += __shfl_xor_sync(0xffffffffu, sum1, 2);
        l0 = l0 * corr0 + sum0;
        l1 = l1 * corr1 + sum1;
        #pragma unroll
        for (int dt = 0; dt < 8; dt++) {
            oacc[dt][0] *= corr0; oacc[dt][1] *= corr0;
            oacc[dt][2] *= corr1; oacc[dt][3] *= corr1;
        }

        // ---- O += P V (3-term) ----
        #pragma unroll
        for (int ts = 0; ts < 4; ts++) {
            float p00 = s[2*ts][0], p01 = s[2*ts][1], p02 = s[2*ts][2], p03 = s[2*ts][3];
            float p10 = s[2*ts+1][0], p11 = s[2*ts+1][1], p12 = s[2*ts+1][2], p13 = s[2*ts+1][3];
            float h00 = bfround(p00), h01 = bfround(p01), h02 = bfround(p02), h03 = bfround(p03);
            float h10 = bfround(p10), h11 = bfround(p11), h12 = bfround(p12), h13 = bfround(p13);
            uint32_t aPh[4], aPl[4];
            aPh[0] = pack_bf16(h00, h01); aPh[1] = pack_bf16(h02, h03);
            aPh[2] = pack_bf16(h10, h11); aPh[3] = pack_bf16(h12, h13);
            aPl[0] = pack_bf16(p00 - h00, p01 - h01); aPl[1] = pack_bf16(p02 - h02, p03 - h03);
            aPl[2] = pack_bf16(p10 - h10, p11 - h11); aPl[3] = pack_bf16(p12 - h12, p13 - h13);

            uint32_t vbh[4][4], vbl[4][4];
            #pragma unroll
            for (int dp = 0; dp < 4; dp++) {
                uint32_t va = sb + 24576 + (uint32_t)(ts * 2304 + dp * 32) + offV;
                ldsm4t(vbh[dp], va);
                ldsm4t(vbl[dp], va + 9216);
            }
            #pragma unroll
            for (int dt = 0; dt < 8; dt++) {
                mma16816(oacc[dt], aPh, &vbh[dt >> 1][(dt & 1) * 2]);
                mma16816(oacc[dt], aPl, &vbh[dt >> 1][(dt & 1) * 2]);
                mma16816(oacc[dt], aPh, &vbl[dt >> 1][(dt & 1) * 2]);
            }
        }
        __syncthreads();
        if (kt + 2 < ktmax) load_kv(kt + 2);
    }

    // ---- epilogue: normalize, hi/lo bf16 to (B,S,D) ----
    const float inv0 = (l0 > 0.f) ? (1.f / l0) : 0.f;
    const float inv1 = (l1 > 0.f) ? (1.f / l1) : 0.f;
    const size_t o0 = ((size_t)(b * SS + grow0)) * DD + h * HD;
    const size_t o1 = ((size_t)(b * SS + grow1)) * DD + h * HD;
    #pragma unroll
    for (int dt = 0; dt < 8; dt++) {
        int dc = dt * 8 + tig2;
        float v0 = oacc[dt][0] * inv0, v1 = oacc[dt][1] * inv0;
        float v2 = oacc[dt][2] * inv1, v3 = oacc[dt][3] * inv1;
        __nv_bfloat16 h0 = __float2bfloat16(v0), h1 = __float2bfloat16(v1);
        __nv_bfloat16 h2 = __float2bfloat16(v2), h3 = __float2bfloat16(v3);
        __nv_bfloat162 hp0 = __nv_bfloat162(h0, h1), hp1 = __nv_bfloat162(h2, h3);
        __nv_bfloat162 lp0 = __nv_bfloat162(
            __float2bfloat16(v0 - __bfloat162float(h0)),
            __float2bfloat16(v1 - __bfloat162float(h1)));
        __nv_bfloat162 lp1 = __nv_bfloat162(
            __float2bfloat16(v2 - __bfloat162float(h2)),
            __float2bfloat16(v3 - __bfloat162float(h3)));
        *(__nv_bfloat162*)&Oh[o0 + dc] = hp0;
        *(__nv_bfloat162*)&Ol[o0 + dc] = lp0;
        *(__nv_bfloat162*)&Oh[o1 + dc] = hp1;
        *(__nv_bfloat162*)&Ol[o1 + dc] = lp1;
    }
}

// ---------------------------------------------------------------------------
extern "C" void kernel_launch(void* const* d_in, const int* in_sizes, int n_in,
                              void* d_out, int out_size)
{
    (void)in_sizes; (void)n_in; (void)out_size;
    const float* x  = (const float*)d_in[0];
    const int*   am = (const int*)d_in[1];
    const float* Wq = (const float*)d_in[2];
    const float* bq = (const float*)d_in[3];
    const float* Wk = (const float*)d_in[4];
    const float* bk = (const float*)d_in[5];
    const float* Wv = (const float*)d_in[6];
    const float* bv = (const float*)d_in[7];
    const float* Wp = (const float*)d_in[8];
    const float* bp = (const float*)d_in[9];
    float* out = (float*)d_out;

    __nv_bfloat16 *xh, *xl, *wh, *wl, *ah, *al;
    __nv_bfloat16 *qh, *ql, *kh, *kl, *vh, *vl;
    cudaGetSymbolAddress((void**)&xh, gx_h);
    cudaGetSymbolAddress((void**)&xl, gx_l);
    cudaGetSymbolAddress((void**)&wh, gw_h);
    cudaGetSymbolAddress((void**)&wl, gw_l);
    cudaGetSymbolAddress((void**)&ah, ga_h);
    cudaGetSymbolAddress((void**)&al, ga_l);
    cudaGetSymbolAddress((void**)&qh, gQh);
    cudaGetSymbolAddress((void**)&ql, gQl);
    cudaGetSymbolAddress((void**)&kh, gKh);
    cudaGetSymbolAddress((void**)&kl, gKl);
    cudaGetSymbolAddress((void**)&vh, gVh);
    cudaGetSymbolAddress((void**)&vl, gVl);

    cudaFuncSetAttribute(tc_gemm,
                         cudaFuncAttributeMaxDynamicSharedMemorySize, GEMM_SMEM);
    cudaFuncSetAttribute(attn_mma,
                         cudaFuncAttributeMaxDynamicSharedMemorySize, ATT_SMEM);

    const int NX = MM * DD;
    const int NW = DD * DD;

    split_bf16<<<NX/1024, 256>>>(x, xh, xl, NX);
    split_bf16<<<NW/1024, 256>>>(Wq, wh + 0*NW, wl + 0*NW, NW);
    split_bf16<<<NW/1024, 256>>>(Wk, wh + 1*NW, wl + 1*NW, NW);
    split_bf16<<<NW/1024, 256>>>(Wv, wh + 2*NW, wl + 2*NW, NW);
    split_bf16<<<NW/1024, 256>>>(Wp, wh + 3*NW, wl + 3*NW, NW);

    dim3 gg(DD/128, MM/128);
    tc_gemm<<<gg, 256, GEMM_SMEM>>>(xh, xl, wh + 0*NW, wl + 0*NW, bq,
                                    nullptr, qh, ql, 2, 0.125f);
    tc_gemm<<<gg, 256, GEMM_SMEM>>>(xh, xl, wh + 1*NW, wl + 1*NW, bk,
                                    nullptr, kh, kl, 2, 1.0f);
    tc_gemm<<<gg, 256, GEMM_SMEM>>>(xh, xl, wh + 2*NW, wl + 2*NW, bv,
                                    nullptr, vh, vl, 2, 1.0f);

    attn_mma<<<dim3(SS/128, HH, BB), 256, ATT_SMEM>>>(qh, ql, kh, kl, vh, vl,
                                                      am, ah, al);

    tc_gemm<<<gg, 256, GEMM_SMEM>>>(ah, al, wh + 3*NW, wl + 3*NW, bp,
                                    out, nullptr, nullptr, 0, 1.0f);
}